// round 2
// baseline (speedup 1.0000x reference)
#include <cuda_runtime.h>
#include <cuda_bf16.h>

// Shapes (fixed by the problem):
// current_pose: (32, 8192, 64) f32       d_in[0]
// w_current:    (1,1,8192,8,8) f32       d_in[1]
// w_next:       (64,8,8) f32             d_in[2]
// E_proj:       (32,256,256) f32         d_in[3]
// rel_embedd:   (1,1,64) f32             d_in[4]
// out:          (32,1,64,64) f32
//
// Algebraic reduction:
//   A[b, hs]   = sum_p (P_{b,n} @ W_n)[i,j],  n = p*128 + q, q = n mod 128,
//                hs = q*64 + i*8 + j  (== h*256 + s of the reference reshape)
//   pooled[b,c]= (1/64) * sum_hs A[b,hs] * F[hs,c],  F[hs,c] = sum_k E[hs, c+64k]
//   out[b,o]   = mat8x8(pooled[b] + rel) @ w_next[o]

__device__ float g_A[32 * 8192];        // A[b][hs]            (1 MB)
__device__ float g_P[128 * 32 * 64];    // partials[kc][b][c]  (1 MB)

// ---------------------------------------------------------------------------
// Kernel 1: per (b, q) compute the 8x8 sum over p of P @ W.
// grid = (32 qg, 32 b), blockDim = 128 (4 warps, 1 q per warp).
// Each warp double-buffers (64 pose floats + 64 w floats) per p through SMEM.
// Lane l: i = l>>2, owns output columns j = 2*(l&3), 2*(l&3)+1.
// ---------------------------------------------------------------------------
__global__ __launch_bounds__(128) void k1_reduce_pose(
    const float* __restrict__ pose, const float* __restrict__ wc)
{
    __shared__ float4 sbuf[4][2][32];   // [warp][buf][32 float4] = 64 P + 64 W

    const int b    = blockIdx.y;
    const int w    = threadIdx.x >> 5;
    const int q    = (blockIdx.x << 2) + w;       // 0..127
    const int lane = threadIdx.x & 31;
    const int i    = lane >> 2;                   // 0..7
    const int jp   = lane & 3;                    // j-pair index

    const float* __restrict__ pose_b = pose + ((size_t)b << 19);  // b*8192*64
    const int off = (lane & 15) << 2;             // float offset within a 64-float row

    // stage p = 0 into buffer 0
    {
        const int n = q;
        const float* s = (lane < 16) ? (pose_b + n * 64 + off)
                                     : (wc     + n * 64 + off);
        sbuf[w][0][lane] = *(const float4*)s;
    }

    float a0 = 0.f, a1 = 0.f;
    #pragma unroll 2
    for (int p = 0; p < 64; ++p) {
        __syncwarp();
        if (p < 63) {   // prefetch next p into the other buffer
            const int n = (p + 1) * 128 + q;
            const float* s = (lane < 16) ? (pose_b + n * 64 + off)
                                         : (wc     + n * 64 + off);
            sbuf[w][(p + 1) & 1][lane] = *(const float4*)s;
        }
        const float* sP = (const float*)&sbuf[w][p & 1][0];
        const float* sW = sP + 64;
        const float4 pa = *(const float4*)(sP + i * 8);
        const float4 pb = *(const float4*)(sP + i * 8 + 4);
        const float pr[8] = {pa.x, pa.y, pa.z, pa.w, pb.x, pb.y, pb.z, pb.w};
        #pragma unroll
        for (int m = 0; m < 8; ++m) {
            const float2 wv = *(const float2*)(sW + m * 8 + jp * 2);
            a0 = fmaf(pr[m], wv.x, a0);
            a1 = fmaf(pr[m], wv.y, a1);
        }
    }

    const int e = i * 8 + jp * 2;
    float2* dst = (float2*)(g_A + ((size_t)b << 13) + (q << 6) + e);
    *dst = make_float2(a0, a1);
}

// ---------------------------------------------------------------------------
// Kernel 2: partial GEMM  part[kc][b][c] = sum_{hs in [kc*64,kc*64+64)} A[b,hs]*F[hs,c]
// with F folded on the fly from E rows.  grid = 512 (kc = bx&127, bg = bx>>7),
// blockDim = 256. Thread t: c = t&63, handles batches b0 = bg*8 + 2*(t>>6), b0+1.
// ---------------------------------------------------------------------------
__global__ __launch_bounds__(256) void k2_gemm(
    const float* __restrict__ E)
{
    __shared__ float sE[2048];   // 8 E rows of 256
    __shared__ float sA[64];     // [bb][r]  8 batches x 8 rows

    const int kc = blockIdx.x & 127;
    const int bg = blockIdx.x >> 7;       // 0..3 (8 batches each)
    const int t  = threadIdx.x;
    const int c  = t & 63;
    const int br = t >> 6;                // 0..3

    float acc0 = 0.f, acc1 = 0.f;
    const int hs0 = kc << 6;

    for (int it = 0; it < 8; ++it) {
        const int hsb = hs0 + (it << 3);
        // stage 8 E rows (2048 floats) — fully coalesced
        {
            const float4* src = (const float4*)(E + (size_t)hsb * 256);
            float4* d4 = (float4*)sE;
            d4[t * 2]     = src[t * 2];
            d4[t * 2 + 1] = src[t * 2 + 1];
        }
        if (t < 64) {  // sA[bb*8 + r]
            const int r = t & 7, bb = t >> 3;
            sA[t] = g_A[(size_t)(bg * 8 + bb) * 8192 + hsb + r];
        }
        __syncthreads();
        #pragma unroll
        for (int r = 0; r < 8; ++r) {
            const float* row = sE + (r << 8);
            const float F = row[c] + row[c + 64] + row[c + 128] + row[c + 192];
            acc0 = fmaf(sA[(br * 2)     * 8 + r], F, acc0);
            acc1 = fmaf(sA[(br * 2 + 1) * 8 + r], F, acc1);
        }
        __syncthreads();
    }

    const int b0 = bg * 8 + br * 2;
    g_P[(kc << 11) + (b0 << 6) + c]       = acc0;
    g_P[(kc << 11) + ((b0 + 1) << 6) + c] = acc1;
}

// ---------------------------------------------------------------------------
// Kernel 3: per b, reduce 128 partials -> pooled, add rel, /64, then
// out[b,o,i,j] = sum_m (pooled+rel)[i*8+m] * w_next[o,m,j].
// grid = 32, blockDim = 256.
// ---------------------------------------------------------------------------
__global__ __launch_bounds__(256) void k3_final(
    const float* __restrict__ rel, const float* __restrict__ wn,
    float* __restrict__ out)
{
    __shared__ float swn[4096];
    __shared__ float sred[4][64];
    __shared__ float su[64];

    const int b = blockIdx.x;
    const int t = threadIdx.x;

    // stage w_next (16 KB) into smem
    {
        const float4* s = (const float4*)wn;
        float4* d = (float4*)swn;
        #pragma unroll
        for (int k = 0; k < 4; ++k) d[t + k * 256] = s[t + k * 256];
    }
    // reduce 128 partials, 4-way parallel over kc
    {
        const int c = t & 63, g = t >> 6;
        float s = 0.f;
        #pragma unroll 8
        for (int kc = g; kc < 128; kc += 4)
            s += g_P[(kc << 11) + (b << 6) + c];
        sred[g][c] = s;
    }
    __syncthreads();
    if (t < 64)
        su[t] = (sred[0][t] + sred[1][t] + sred[2][t] + sred[3][t]) * (1.0f / 64.0f)
                + rel[t];
    __syncthreads();

    for (int idx = t; idx < 4096; idx += 256) {
        const int o = idx >> 6, i = (idx >> 3) & 7, j = idx & 7;
        const float* u = su + i * 8;
        const float* W = swn + o * 64 + j;
        float acc = 0.f;
        #pragma unroll
        for (int m = 0; m < 8; ++m)
            acc = fmaf(u[m], W[m * 8], acc);
        out[(b << 12) + idx] = acc;
    }
}

// ---------------------------------------------------------------------------
extern "C" void kernel_launch(void* const* d_in, const int* in_sizes, int n_in,
                              void* d_out, int out_size)
{
    const float* pose = (const float*)d_in[0];
    const float* wc   = (const float*)d_in[1];
    const float* wn   = (const float*)d_in[2];
    const float* E    = (const float*)d_in[3];
    const float* rel  = (const float*)d_in[4];
    float* out        = (float*)d_out;

    dim3 g1(32, 32);
    k1_reduce_pose<<<g1, 128>>>(pose, wc);
    k2_gemm<<<512, 256>>>(E);
    k3_final<<<32, 256>>>(rel, wn, out);
}

// round 4
// speedup vs baseline: 1.5325x; 1.5325x over previous
#include <cuda_runtime.h>
#include <cuda_bf16.h>
#include <cstdint>

// Shapes:
// current_pose: (32, 8192, 64) f32   d_in[0]
// w_current:    (8192, 8, 8) f32     d_in[1]
// w_next:       (64, 8, 8) f32       d_in[2]
// E_proj:       (32, 256, 256) f32   d_in[3]
// rel_embedd:   (64,) f32            d_in[4]
// out:          (32, 64, 64) f32
//
// A[b, hs] = sum_p (P_{b,n} @ W_n)[i,j], n = p*128 + q, hs = q*64 + i*8 + j
// pooled[b,c] = (1/64) * sum_hs A[b,hs] * F[hs,c], F[hs,c] = sum_k E[hs, c+64k]
// out[b,o] = mat8x8(pooled[b] + rel) @ w_next[o]

#define K1_STAGES 6
#define K1_NP 32            // p-steps per block (p split in 2)

__device__ float g_Ap[2 * 32 * 8192];   // partial A per pg  (2 MB)
__device__ float g_P[256 * 32 * 64];    // partials[kc][b][c] (2 MB)

// ---- packed f32x2 helpers (sm_100) --------------------------------------
__device__ __forceinline__ unsigned long long pk2(float x, float y) {
    unsigned long long r;
    asm("mov.b64 %0, {%1,%2};" : "=l"(r) : "f"(x), "f"(y));
    return r;
}
__device__ __forceinline__ void upk2(unsigned long long v, float& x, float& y) {
    asm("mov.b64 {%0,%1}, %2;" : "=f"(x), "=f"(y) : "l"(v));
}
__device__ __forceinline__ void ffma2(unsigned long long& d,
                                      unsigned long long a, unsigned long long b) {
    asm("fma.rn.f32x2 %0, %1, %2, %0;" : "+l"(d) : "l"(a), "l"(b));
}
// ---- cp.async helpers ----------------------------------------------------
__device__ __forceinline__ void cp16(unsigned int dst, const void* src) {
    asm volatile("cp.async.cg.shared.global [%0], [%1], 16;" :: "r"(dst), "l"(src));
}
__device__ __forceinline__ void cp_commit() { asm volatile("cp.async.commit_group;"); }
template <int N>
__device__ __forceinline__ void cp_wait() { asm volatile("cp.async.wait_group %0;" :: "n"(N)); }

__device__ __forceinline__ unsigned int smem_u32(const void* p) {
    return (unsigned int)__cvta_generic_to_shared(p);
}

// ---------------------------------------------------------------------------
// Kernel 1: grid (128 q, 2 bg, 2 pg), block 128 = 16 batches x 8 i-rows.
// Per p-step: stage 16 P rows (16x64 f32, padded to 68) + 1 W row (64 f32),
// 6-deep cp.async pipeline. Thread (b,i) computes 8 outputs (4 f32x2 accums).
// ---------------------------------------------------------------------------
__global__ __launch_bounds__(128) void k1_reduce_pose(
    const float* __restrict__ pose, const float* __restrict__ wc)
{
    __shared__ float sP[K1_STAGES][16 * 68];   // padded rows: stride 68 floats
    __shared__ float sW[K1_STAGES][64];

    const int t  = threadIdx.x;
    const int q  = blockIdx.x;
    const int bg = blockIdx.y;
    const int pg = blockIdx.z;
    const int p0 = pg * K1_NP;

    const int r  = t >> 3;          // staging row / batch-in-block 0..15
    const int s8 = (t & 7) * 8;     // staging segment (floats)
    const int bglob = bg * 16 + r;

    const float* psrc = pose + ((size_t)bglob << 19) + s8;      // + n*64 later
    const float* wsrc = wc + (t & 15) * 4;
    const unsigned int pd = smem_u32(&sP[0][r * 68 + s8]);
    const unsigned int wd = smem_u32(&sW[0][(t & 15) * 4]);
    const bool doW = (t < 16);
    const unsigned int STP = 16 * 68 * 4;   // bytes per P stage
    const unsigned int STW = 64 * 4;        // bytes per W stage

    auto issue = [&](int k) {
        const unsigned int slot = (unsigned int)(k % K1_STAGES);
        const size_t noff = (size_t)((p0 + k) * 128 + q) * 64;
        cp16(pd + slot * STP,      psrc + noff);
        cp16(pd + slot * STP + 16, psrc + noff + 4);
        if (doW) cp16(wd + slot * STW, wsrc + noff);
        cp_commit();
    };

    #pragma unroll
    for (int k = 0; k < K1_STAGES - 1; ++k) issue(k);

    const int b = t >> 3, i = t & 7;
    unsigned long long a0 = 0, a1 = 0, a2 = 0, a3 = 0;

    for (int k = 0; k < K1_NP; ++k) {
        cp_wait<K1_STAGES - 2>();
        __syncthreads();
        if (k + K1_STAGES - 1 < K1_NP) issue(k + K1_STAGES - 1);
        else cp_commit();

        const int slot = k % K1_STAGES;
        const float* prow = &sP[slot][b * 68 + i * 8];
        const float4 pa = *(const float4*)prow;
        const float4 pb = *(const float4*)(prow + 4);
        const float pr[8] = {pa.x, pa.y, pa.z, pa.w, pb.x, pb.y, pb.z, pb.w};
        const float4* w4 = (const float4*)sW[slot];
        #pragma unroll
        for (int m = 0; m < 8; ++m) {
            const unsigned long long pm = pk2(pr[m], pr[m]);
            const float4 w0 = w4[m * 2];
            const float4 w1 = w4[m * 2 + 1];
            ffma2(a0, pm, pk2(w0.x, w0.y));
            ffma2(a1, pm, pk2(w0.z, w0.w));
            ffma2(a2, pm, pk2(w1.x, w1.y));
            ffma2(a3, pm, pk2(w1.z, w1.w));
        }
    }

    float4 o0, o1;
    upk2(a0, o0.x, o0.y); upk2(a1, o0.z, o0.w);
    upk2(a2, o1.x, o1.y); upk2(a3, o1.z, o1.w);
    float* dst = g_Ap + ((size_t)(pg * 32 + bglob) << 13) + (q << 6) + i * 8;
    *(float4*)dst = o0;
    *(float4*)(dst + 4) = o1;
}

// ---------------------------------------------------------------------------
// Kernel 2: grid 256 (kc -> hs chunk of 32 rows), block 256. Reads E rows ONCE
// for all 32 batches. Folds the two p-partials of A. 3-slot cp.async E pipe.
// part[kc][b][c] = sum_{rr<32} A[b, kc*32+rr] * F[kc*32+rr, c]
// ---------------------------------------------------------------------------
__global__ __launch_bounds__(256) void k2_gemm(const float* __restrict__ E)
{
    __shared__ float sE[3][2048];   // 8 E rows x 256 per slot
    __shared__ float sA[32 * 32];   // [b][rr]

    const int t   = threadIdx.x;
    const int kc  = blockIdx.x;
    const int hs0 = kc << 5;

    auto issueE = [&](int it) {
        const int sl = it % 3;
        const float4* src = (const float4*)(E + (size_t)(hs0 + it * 8) * 256);
        const unsigned int d = smem_u32(&sE[sl][0]) + t * 32;
        cp16(d,      src + t * 2);
        cp16(d + 16, src + t * 2 + 1);
        cp_commit();
    };

    issueE(0);

    // stage A chunk: 32 b x 32 rr, summing the two p-partials
    #pragma unroll
    for (int j = 0; j < 4; ++j) {
        const int idx = t + 256 * j;
        const int bb = idx >> 5, rr = idx & 31;
        sA[idx] = g_Ap[(size_t)bb * 8192 + hs0 + rr]
                + g_Ap[(size_t)(bb + 32) * 8192 + hs0 + rr];
    }

    const int c = t & 63, g = t >> 6;
    float acc[8] = {0, 0, 0, 0, 0, 0, 0, 0};

    for (int it = 0; it < 4; ++it) {
        if (it + 1 < 4) issueE(it + 1);
        else cp_commit();
        cp_wait<1>();
        __syncthreads();

        const float* e = sE[it % 3];
        #pragma unroll
        for (int rr2 = 0; rr2 < 8; ++rr2) {
            const float* row = e + (rr2 << 8);
            const float F = row[c] + row[c + 64] + row[c + 128] + row[c + 192];
            const int rr = it * 8 + rr2;
            #pragma unroll
            for (int bb = 0; bb < 8; ++bb)
                acc[bb] = fmaf(sA[(g * 8 + bb) * 32 + rr], F, acc[bb]);
        }
        __syncthreads();
    }

    #pragma unroll
    for (int bb = 0; bb < 8; ++bb)
        g_P[((size_t)kc << 11) + ((g * 8 + bb) << 6) + c] = acc[bb];
}

// ---------------------------------------------------------------------------
// Kernel 3: per b, reduce 256 partials -> pooled, /64 + rel, then 8x8 epilogue.
// ---------------------------------------------------------------------------
__global__ __launch_bounds__(256) void k3_final(
    const float* __restrict__ rel, const float* __restrict__ wn,
    float* __restrict__ out)
{
    __shared__ float swn[4096];
    __shared__ float sred[4][64];
    __shared__ float su[64];

    const int b = blockIdx.x;
    const int t = threadIdx.x;

    {
        const float4* s = (const float4*)wn;
        float4* d = (float4*)swn;
        #pragma unroll
        for (int k = 0; k < 4; ++k) d[t + k * 256] = s[t + k * 256];
    }
    {
        const int c = t & 63, g = t >> 6;
        float s = 0.f;
        #pragma unroll 8
        for (int kc = g; kc < 256; kc += 4)
            s += g_P[((size_t)kc << 11) + (b << 6) + c];
        sred[g][c] = s;
    }
    __syncthreads();
    if (t < 64)
        su[t] = (sred[0][t] + sred[1][t] + sred[2][t] + sred[3][t]) * (1.0f / 64.0f)
                + rel[t];
    __syncthreads();

    for (int idx = t; idx < 4096; idx += 256) {
        const int o = idx >> 6, i = (idx >> 3) & 7, j = idx & 7;
        const float* u = su + i * 8;
        const float* W = swn + o * 64 + j;
        float acc = 0.f;
        #pragma unroll
        for (int m = 0; m < 8; ++m)
            acc = fmaf(u[m], W[m * 8], acc);
        out[(b << 12) + idx] = acc;
    }
}

// ---------------------------------------------------------------------------
extern "C" void kernel_launch(void* const* d_in, const int* in_sizes, int n_in,
                              void* d_out, int out_size)
{
    const float* pose = (const float*)d_in[0];
    const float* wc   = (const float*)d_in[1];
    const float* wn   = (const float*)d_in[2];
    const float* E    = (const float*)d_in[3];
    const float* rel  = (const float*)d_in[4];
    float* out        = (float*)d_out;

    dim3 g1(128, 2, 2);
    k1_reduce_pose<<<g1, 128>>>(pose, wc);
    k2_gemm<<<256, 256>>>(E);
    k3_final<<<32, 256>>>(rel, wn, out);
}

// round 5
// speedup vs baseline: 1.7871x; 1.1661x over previous
#include <cuda_runtime.h>
#include <cuda_bf16.h>
#include <cstdint>

// Shapes:
// current_pose: (32, 8192, 64) f32   d_in[0]
// w_current:    (8192, 8, 8) f32     d_in[1]
// w_next:       (64, 8, 8) f32       d_in[2]
// E_proj:       (32, 256, 256) f32   d_in[3]
// rel_embedd:   (64,) f32            d_in[4]
// out:          (32, 64, 64) f32
//
// A[b, hs] = sum_p (P_{b,n} @ W_n)[i,j], n = p*128 + q, hs = q*64 + i*8 + j
// pooled[b,c] = (1/64) * sum_hs A[b,hs] * F[hs,c], F[hs,c] = sum_k E[hs, c+64k]
// out[b,o] = mat8x8(pooled[b] + rel) @ w_next[o]

#define K1_PG 4
#define K1_NP 16            // p-steps per block (p split 4 ways)

__device__ float g_Ap[K1_PG * 32 * 8192];   // partial A per pg  (4 MB)
__device__ float g_P[256 * 32 * 64];        // partials[kc][b][c] (2 MB)

// ---- packed f32x2 helpers (sm_100) --------------------------------------
__device__ __forceinline__ unsigned long long pk2(float x, float y) {
    unsigned long long r;
    asm("mov.b64 %0, {%1,%2};" : "=l"(r) : "f"(x), "f"(y));
    return r;
}
__device__ __forceinline__ void upk2(unsigned long long v, float& x, float& y) {
    asm("mov.b64 {%0,%1}, %2;" : "=f"(x), "=f"(y) : "l"(v));
}
__device__ __forceinline__ void ffma2(unsigned long long& d,
                                      unsigned long long a, unsigned long long b) {
    asm("fma.rn.f32x2 %0, %1, %2, %0;" : "+l"(d) : "l"(a), "l"(b));
}
// ---- cp.async helpers ----------------------------------------------------
__device__ __forceinline__ void cp16(unsigned int dst, const void* src) {
    asm volatile("cp.async.cg.shared.global [%0], [%1], 16;" :: "r"(dst), "l"(src));
}
__device__ __forceinline__ void cp_commit() { asm volatile("cp.async.commit_group;"); }
template <int N>
__device__ __forceinline__ void cp_wait() { asm volatile("cp.async.wait_group %0;" :: "n"(N)); }

__device__ __forceinline__ unsigned int smem_u32(const void* p) {
    return (unsigned int)__cvta_generic_to_shared(p);
}

// ---------------------------------------------------------------------------
// Kernel 1: grid (128 q, 2 bg, 4 pg), block 128 = 16 batches x 8 i-rows.
// All 16 W rows staged once (4 KB). P rows loaded straight to registers with
// a lookahead-2 double buffer. No barriers in the main loop.
// ---------------------------------------------------------------------------
__global__ __launch_bounds__(128) void k1_reduce_pose(
    const float* __restrict__ pose, const float* __restrict__ wc)
{
    __shared__ float sW[K1_NP][64];    // 4 KB

    const int t  = threadIdx.x;
    const int q  = blockIdx.x;
    const int bg = blockIdx.y;
    const int pg = blockIdx.z;
    const int p0 = pg * K1_NP;

    // stage all W rows: row k = t>>3, 8-float segment seg = t&7
    {
        const int k = t >> 3, seg = t & 7;
        const float* src = wc + ((size_t)(p0 + k) * 128 + q) * 64 + seg * 8;
        const unsigned int d = smem_u32(&sW[k][seg * 8]);
        cp16(d, src);
        cp16(d + 16, src + 4);
        cp_commit();
    }

    const int b = t >> 3, i = t & 7;
    const int bglob = bg * 16 + b;
    // pose element [bglob, (p0+k)*128+q, i*8+m]
    const float* prow = pose + ((size_t)bglob << 19)
                             + ((size_t)(p0 * 128 + q) << 6) + i * 8;
    const size_t PSTEP = 128 * 64;     // floats per p-step

    float4 cb[2][2];
    cb[0][0] = *(const float4*)(prow);
    cb[0][1] = *(const float4*)(prow + 4);
    cb[1][0] = *(const float4*)(prow + PSTEP);
    cb[1][1] = *(const float4*)(prow + PSTEP + 4);

    cp_wait<0>();
    __syncthreads();

    unsigned long long a0 = 0, a1 = 0, a2 = 0, a3 = 0;

    #pragma unroll
    for (int k = 0; k < K1_NP; ++k) {
        const float4 pa = cb[k & 1][0];
        const float4 pb = cb[k & 1][1];
        if (k + 2 < K1_NP) {
            cb[k & 1][0] = *(const float4*)(prow + (size_t)(k + 2) * PSTEP);
            cb[k & 1][1] = *(const float4*)(prow + (size_t)(k + 2) * PSTEP + 4);
        }
        const float pr[8] = {pa.x, pa.y, pa.z, pa.w, pb.x, pb.y, pb.z, pb.w};
        const ulonglong2* w2 = (const ulonglong2*)&sW[k][0];
        #pragma unroll
        for (int m = 0; m < 8; ++m) {
            const unsigned long long pm = pk2(pr[m], pr[m]);
            const ulonglong2 wa = w2[m * 2];       // j0..3 packed
            const ulonglong2 wb = w2[m * 2 + 1];   // j4..7 packed
            ffma2(a0, pm, wa.x);
            ffma2(a1, pm, wa.y);
            ffma2(a2, pm, wb.x);
            ffma2(a3, pm, wb.y);
        }
    }

    float4 o0, o1;
    upk2(a0, o0.x, o0.y); upk2(a1, o0.z, o0.w);
    upk2(a2, o1.x, o1.y); upk2(a3, o1.z, o1.w);
    float* dst = g_Ap + ((size_t)(pg * 32 + bglob) << 13) + (q << 6) + i * 8;
    *(float4*)dst = o0;
    *(float4*)(dst + 4) = o1;
}

// ---------------------------------------------------------------------------
// Kernel 2: grid 256 (kc -> 32 hs rows), block 256. E rows read ONCE for all
// 32 batches; all 4 E stages issued upfront; folds the 4 p-partials of A.
// part[kc][b][c] = sum_{rr<32} A[b, kc*32+rr] * F[kc*32+rr, c]
// ---------------------------------------------------------------------------
__global__ __launch_bounds__(256) void k2_gemm(const float* __restrict__ E)
{
    __shared__ float sE[4][2048];   // 4 stages x 8 E rows x 256  (32 KB)
    __shared__ float sA[32 * 32];   // [b][rr]

    const int t   = threadIdx.x;
    const int kc  = blockIdx.x;
    const int hs0 = kc << 5;

    // issue all 4 E stages now
    #pragma unroll
    for (int it = 0; it < 4; ++it) {
        const float4* src = (const float4*)(E + (size_t)(hs0 + it * 8) * 256);
        const unsigned int d = smem_u32(&sE[it][0]) + t * 32;
        cp16(d,      src + t * 2);
        cp16(d + 16, src + t * 2 + 1);
        cp_commit();
    }

    // stage A chunk (overlaps with E loads): 32 b x 32 rr, folding 4 partials
    #pragma unroll
    for (int j = 0; j < 4; ++j) {
        const int idx = t + 256 * j;
        const int bb = idx >> 5, rr = idx & 31;
        float s = 0.f;
        #pragma unroll
        for (int pp = 0; pp < K1_PG; ++pp)
            s += g_Ap[((size_t)(pp * 32 + bb) << 13) + hs0 + rr];
        sA[idx] = s;
    }

    const int c = t & 63, g = t >> 6;
    float acc[8] = {0, 0, 0, 0, 0, 0, 0, 0};

    #pragma unroll
    for (int it = 0; it < 4; ++it) {
        if (it == 0)      cp_wait<3>();
        else if (it == 1) cp_wait<2>();
        else if (it == 2) cp_wait<1>();
        else              cp_wait<0>();
        __syncthreads();

        const float* e = sE[it];
        #pragma unroll
        for (int rr2 = 0; rr2 < 8; ++rr2) {
            const float* row = e + (rr2 << 8);
            const float F = row[c] + row[c + 64] + row[c + 128] + row[c + 192];
            const int rr = it * 8 + rr2;
            #pragma unroll
            for (int bb = 0; bb < 8; ++bb)
                acc[bb] = fmaf(sA[(g * 8 + bb) * 32 + rr], F, acc[bb]);
        }
    }

    #pragma unroll
    for (int bb = 0; bb < 8; ++bb)
        g_P[((size_t)kc << 11) + ((g * 8 + bb) << 6) + c] = acc[bb];
}

// ---------------------------------------------------------------------------
// Kernel 3: per b, reduce 256 partials -> pooled, /64 + rel, then 8x8 epilogue.
// ---------------------------------------------------------------------------
__global__ __launch_bounds__(256) void k3_final(
    const float* __restrict__ rel, const float* __restrict__ wn,
    float* __restrict__ out)
{
    __shared__ float swn[4096];
    __shared__ float sred[4][64];
    __shared__ float su[64];

    const int b = blockIdx.x;
    const int t = threadIdx.x;

    {
        const float4* s = (const float4*)wn;
        float4* d = (float4*)swn;
        #pragma unroll
        for (int k = 0; k < 4; ++k) d[t + k * 256] = s[t + k * 256];
    }
    {
        const int c = t & 63, g = t >> 6;
        float s = 0.f;
        #pragma unroll 8
        for (int kc = g; kc < 256; kc += 4)
            s += g_P[((size_t)kc << 11) + (b << 6) + c];
        sred[g][c] = s;
    }
    __syncthreads();
    if (t < 64)
        su[t] = (sred[0][t] + sred[1][t] + sred[2][t] + sred[3][t]) * (1.0f / 64.0f)
                + rel[t];
    __syncthreads();

    for (int idx = t; idx < 4096; idx += 256) {
        const int o = idx >> 6, i = (idx >> 3) & 7, j = idx & 7;
        const float* u = su + i * 8;
        const float* W = swn + o * 64 + j;
        float acc = 0.f;
        #pragma unroll
        for (int m = 0; m < 8; ++m)
            acc = fmaf(u[m], W[m * 8], acc);
        out[(b << 12) + idx] = acc;
    }
}

// ---------------------------------------------------------------------------
extern "C" void kernel_launch(void* const* d_in, const int* in_sizes, int n_in,
                              void* d_out, int out_size)
{
    const float* pose = (const float*)d_in[0];
    const float* wc   = (const float*)d_in[1];
    const float* wn   = (const float*)d_in[2];
    const float* E    = (const float*)d_in[3];
    const float* rel  = (const float*)d_in[4];
    float* out        = (float*)d_out;

    dim3 g1(128, 2, 4);
    k1_reduce_pose<<<g1, 128>>>(pose, wc);
    k2_gemm<<<256, 256>>>(E);
    k3_final<<<32, 256>>>(rel, wn, out);
}